// round 7
// baseline (speedup 1.0000x reference)
#include <cuda_runtime.h>
#include <cuda_bf16.h>
#include <cstdint>

// ChannelBlockImportanceGate: forward value == hard top-k block mask.
// features [8,256,132,132] f32, enabled int32. BLOCK=8 -> 17x17=289 blocks,
// keep = 72. Ties: lower flat index wins (lax.top_k).
//
// R7: barrier-free Phase A. Each lane stages only the 32B it consumes via
// cp.async into a private smem slot ring (DEPTH=4); per-lane wait_group is
// the only synchronization until Phase A completes. One __syncthreads total
// for the load phase (vs 18 in R6). Reduction trees bitwise identical to
// all passing rounds.

#define HH   132
#define WW   132
#define NBX  17
#define NBLK 289
#define KEEP 72
#define NPIX (HH*WW)
#define NTHREADS 256
#define DEPTH 4

__device__ __forceinline__ void cp_async16(void* smem_ptr, const void* gptr) {
    uint32_t s = (uint32_t)__cvta_generic_to_shared(smem_ptr);
    asm volatile("cp.async.cg.shared.global [%0], [%1], 16;\n"
                 :: "r"(s), "l"(gptr));
}
#define CP_COMMIT() asm volatile("cp.async.commit_group;\n" ::: "memory")
#define CP_WAITD()  asm volatile("cp.async.wait_group %0;\n" :: "n"(DEPTH-1) : "memory")
#define CP_WAIT0()  asm volatile("cp.async.wait_group 0;\n" ::: "memory")

struct LaneSlot { float4 a; float4 b; };   // 32 B

__global__ __launch_bounds__(NTHREADS)
void gate_kernel(const float* __restrict__ in,
                 const int*  __restrict__ enabled,
                 float* __restrict__ out)
{
    const int bc = blockIdx.x;
    const long long base = (long long)bc * NPIX;
    const int tid  = threadIdx.x;
    const int warp = tid >> 5;
    const int lane = tid & 31;

    if (*enabled == 0) {
        float4 ones = make_float4(1.f, 1.f, 1.f, 1.f);
        float4* o4 = (float4*)(out + base);
        for (int p = tid; p < NPIX / 4; p += NTHREADS) o4[p] = ones;
        return;
    }

    __shared__ LaneSlot buf[8][DEPTH][NBX];   // 8*4*17*32 = 17408 B
    __shared__ float  rbs[HH * NBX];
    __shared__ float  pooled[NBLK];
    __shared__ float  hardm[NBLK];
    __shared__ int    hist[32];
    __shared__ float  wmin[8], wmax[8];
    __shared__ float  s_minv, s_scale;
    __shared__ int    s_bb, s_chi, s_mcnt;
    __shared__ int    bblist[NBLK];

    if (tid < 32) hist[tid] = 0;
    if (tid == 0) s_mcnt = 0;

    const float* src = in + base;

    // ---- Phase A: lane-private cp.async ring; warp w owns rows w, w+8, ...
    if (lane < NBX) {
        const int nrows = (HH - warp + 7) >> 3;        // 17 (w<4) or 16
        const float* gl = src + lane * 8;              // lane's column offset
        const bool hasb = (lane < 16);

        // prefill DEPTH-1 rows (one commit group per row)
        #pragma unroll
        for (int i = 0; i < DEPTH - 1; i++) {
            if (i < nrows) {
                const float* g = gl + (warp + (i << 3)) * WW;
                cp_async16(&buf[warp][i][lane].a, g);
                if (hasb) cp_async16(&buf[warp][i][lane].b, g + 4);
            }
            CP_COMMIT();
        }

        for (int i = 0; i < nrows; i++) {
            // issue row i+DEPTH-1 (or empty group to keep the count invariant)
            int ip = i + DEPTH - 1;
            if (ip < nrows) {
                const float* g = gl + (warp + (ip << 3)) * WW;
                cp_async16(&buf[warp][ip & (DEPTH - 1)][lane].a, g);
                if (hasb) cp_async16(&buf[warp][ip & (DEPTH - 1)][lane].b, g + 4);
            }
            CP_COMMIT();
            CP_WAITD();                                 // row i's group done

            LaneSlot* s = &buf[warp][i & (DEPTH - 1)][lane];
            float4 a = s->a;
            float4 b = hasb ? s->b : make_float4(0.f, 0.f, 0.f, 0.f);
            int y = warp + (i << 3);
            rbs[y * NBX + lane] =
                  ((fabsf(a.x) + fabsf(b.x)) + (fabsf(a.z) + fabsf(b.z)))
                + ((fabsf(a.y) + fabsf(b.y)) + (fabsf(a.w) + fabsf(b.w)));
        }
    }
    CP_WAIT0();
    __syncthreads();

    // ---- Phase B: block sums (linear over 8 rows, rows>=132 are pad) + min/max.
    float lmin = 3.4e38f, lmax = -3.4e38f;
    for (int b = tid; b < NBLK; b += NTHREADS) {
        int by = b / NBX;
        int bx = b - by * NBX;
        int y0 = by * 8;
        float s = 0.0f;
        #pragma unroll
        for (int r = 0; r < 8; r++) {
            int y = y0 + r;
            if (y < HH) s += rbs[y * NBX + bx];
        }
        pooled[b] = s;
        lmin = fminf(lmin, s);
        lmax = fmaxf(lmax, s);
    }
    #pragma unroll
    for (int off = 16; off > 0; off >>= 1) {
        lmin = fminf(lmin, __shfl_down_sync(0xffffffffu, lmin, off));
        lmax = fmaxf(lmax, __shfl_down_sync(0xffffffffu, lmax, off));
    }
    if (lane == 0) { wmin[warp] = lmin; wmax[warp] = lmax; }
    __syncthreads();

    // ---- warp 0: global min/max -> bin scale
    if (warp == 0) {
        float mn = (lane < 8) ? wmin[lane] : 3.4e38f;
        float mx = (lane < 8) ? wmax[lane] : -3.4e38f;
        #pragma unroll
        for (int off = 4; off > 0; off >>= 1) {
            mn = fminf(mn, __shfl_down_sync(0xffffffffu, mn, off));
            mx = fmaxf(mx, __shfl_down_sync(0xffffffffu, mx, off));
        }
        if (lane == 0) {
            float r = mx - mn;
            s_minv  = mn;
            s_scale = (r > 0.0f) ? (32.0f / r) : 0.0f;
        }
    }
    __syncthreads();

    // ---- histogram
    {
        float minv = s_minv, scale = s_scale;
        for (int b = tid; b < NBLK; b += NTHREADS) {
            int bin = min((int)((pooled[b] - minv) * scale), 31);
            atomicAdd(&hist[bin], 1);
        }
    }
    __syncthreads();

    // ---- warp 0: suffix scan -> boundary bin bb, count strictly above (chi)
    if (warp == 0) {
        int cge = hist[lane];
        #pragma unroll
        for (int off = 1; off < 32; off <<= 1) {
            int t = __shfl_down_sync(0xffffffffu, cge, off);
            if (lane + off < 32) cge += t;
        }
        int cgt = __shfl_down_sync(0xffffffffu, cge, 1);
        if (lane == 31) cgt = 0;
        if (cgt < KEEP && cge >= KEEP) { s_bb = lane; s_chi = cgt; }
    }
    __syncthreads();

    // ---- classify; collect boundary-bin items
    {
        float minv = s_minv, scale = s_scale;
        int bb = s_bb;
        for (int b = tid; b < NBLK; b += NTHREADS) {
            int bin = min((int)((pooled[b] - minv) * scale), 31);
            if (bin > bb)      hardm[b] = 1.0f;
            else if (bin < bb) hardm[b] = 0.0f;
            else               bblist[atomicAdd(&s_mcnt, 1)] = b;
        }
    }
    __syncthreads();

    // ---- exact rank inside boundary bin (tie: lower index wins)
    {
        int m = s_mcnt;
        int budget = KEEP - s_chi;
        for (int it = tid; it < m; it += NTHREADS) {
            int i = bblist[it];
            float vi = pooled[i];
            int c = 0;
            for (int j = 0; j < m; j++) {
                int jj = bblist[j];
                float vj = pooled[jj];
                c += (vj > vi) || (vj == vi && jj < i);
            }
            hardm[i] = (c < budget) ? 1.0f : 0.0f;
        }
    }
    __syncthreads();

    // ---- Phase D: expand to pixels, float4 stores
    for (int by = warp; by < NBX; by += 8) {
        float  mv  = hardm[by * NBX + (lane >> 1)];
        float  m16 = hardm[by * NBX + 16];
        float4 v4  = make_float4(mv, mv, mv, mv);
        float4 v16 = make_float4(m16, m16, m16, m16);
        int ylim = min(HH - by * 8, 8);
        float* obase = out + base + (by * 8) * WW;
        for (int r = 0; r < ylim; r++) {
            float* orow = obase + r * WW;
            *(float4*)(orow + lane * 4) = v4;
            if (lane == 0) *(float4*)(orow + 128) = v16;
        }
    }
}

extern "C" void kernel_launch(void* const* d_in, const int* in_sizes, int n_in,
                              void* d_out, int out_size)
{
    const float* features = (const float*)d_in[0];
    const int*   enabled  = (const int*)d_in[1];
    float* out = (float*)d_out;

    const int n_channels = out_size / NPIX;   // 2048
    gate_kernel<<<n_channels, NTHREADS>>>(features, enabled, out);
}